// round 1
// baseline (speedup 1.0000x reference)
#include <cuda_runtime.h>

#define H 512
#define W 512
#define BSZ 16
#define CH 3
#define NS (BSZ*CH)          // 48 systems
#define SYS (H*W)            // 262144
#define NTOT (NS*SYS)        // 12582912
#define RTOT (NS*H)          // 24576 total rows
#define WCN (511*512)        // weights_col per batch
#define WRN (512*511)        // weights_row per batch
#define MAXIT 100
#define EPS_F 158.32966f     // (1e-6 * 16*3*512*512)^2
#define TPB 512
#define ROWSTEP (TPB/128)    // 4 rows processed per block step

// Scratch (allocation-free requirement: __device__ globals)
__device__ float g_r[NTOT];
__device__ float g_p[NTOT];
__device__ float g_Ap[NTOT];
__device__ float g_pAp[3][NS*8];
__device__ float g_rr[3][NS*8];
__device__ unsigned int g_bar_arrive;
__device__ volatile unsigned int g_bar_phase;

__device__ __forceinline__ float4 ld4(const float* p) { return *reinterpret_cast<const float4*>(p); }
__device__ __forceinline__ void st4(float* p, float4 v) { *reinterpret_cast<float4*>(p) = v; }

__device__ __forceinline__ float nan0(float v) {
    if (isnan(v)) return 0.0f;
    if (isinf(v)) return v > 0.f ? 3.402823466e38f : -3.402823466e38f;
    return v;
}

// Software grid barrier (all blocks co-resident by construction).
__device__ __forceinline__ void grid_barrier(int G, unsigned int &gen) {
    __syncthreads();
    if (threadIdx.x == 0) {
        __threadfence();
        unsigned int t = atomicAdd(&g_bar_arrive, 1u);
        if (t == (unsigned int)(G - 1)) {
            g_bar_arrive = 0;
            __threadfence();
            g_bar_phase = gen + 1u;
        } else {
            while (g_bar_phase == gen) { __nanosleep(64); }
        }
        gen++;
        __threadfence();
    }
    __syncthreads();
}

// y = (I + L_w) x at (i, j0..j0+3).  Diagonal built on the fly:
// y = x + sum_edges w*(x - x_nbr), guards identical to reference padding.
__device__ __forceinline__ void apply_A(
    const float* __restrict__ xs, const float* __restrict__ wcb,
    const float* __restrict__ wrb, int i, int j0, float4 &xc, float4 &y)
{
    int idx = i * W + j0;
    xc = ld4(xs + idx);
    float y0 = xc.x, y1 = xc.y, y2 = xc.z, y3 = xc.w;
    if (i > 0) {
        float4 xu = ld4(xs + idx - W);
        float4 wu = ld4(wcb + (i - 1) * W + j0);
        y0 += wu.x * (xc.x - xu.x); y1 += wu.y * (xc.y - xu.y);
        y2 += wu.z * (xc.z - xu.z); y3 += wu.w * (xc.w - xu.w);
    }
    if (i < H - 1) {
        float4 xd = ld4(xs + idx + W);
        float4 wd = ld4(wcb + i * W + j0);
        y0 += wd.x * (xc.x - xd.x); y1 += wd.y * (xc.y - xd.y);
        y2 += wd.z * (xc.z - xd.z); y3 += wd.w * (xc.w - xd.w);
    }
    const float* wrow = wrb + i * 511;
    float w0 = wrow[j0], w1 = wrow[j0 + 1], w2 = wrow[j0 + 2];
    y0 += w0 * (xc.x - xc.y);
    y1 += w0 * (xc.y - xc.x) + w1 * (xc.y - xc.z);
    y2 += w1 * (xc.z - xc.y) + w2 * (xc.z - xc.w);
    y3 += w2 * (xc.w - xc.z);
    if (j0 > 0) {
        y0 += wrow[j0 - 1] * (xc.x - xs[idx - 1]);
    }
    if (j0 + 4 < W) {   // column j0+3 < 511 has a right edge
        y3 += wrow[j0 + 3] * (xc.w - xs[idx + 4]);
    }
    y = make_float4(y0, y1, y2, y3);
}

// Block covers contiguous rows within at most 2 systems (s0, s0+1).
__device__ __forceinline__ void reduce2_atomic(float a0, float a1, int s0, int r1, float* dst)
{
    __shared__ float sm[2][TPB / 32];
    #pragma unroll
    for (int o = 16; o; o >>= 1) {
        a0 += __shfl_down_sync(0xffffffffu, a0, o);
        a1 += __shfl_down_sync(0xffffffffu, a1, o);
    }
    int wid = threadIdx.x >> 5, lid = threadIdx.x & 31;
    if (lid == 0) { sm[0][wid] = a0; sm[1][wid] = a1; }
    __syncthreads();
    if (threadIdx.x < 32) {
        a0 = (lid < TPB / 32) ? sm[0][lid] : 0.f;
        a1 = (lid < TPB / 32) ? sm[1][lid] : 0.f;
        #pragma unroll
        for (int o = 16; o; o >>= 1) {
            a0 += __shfl_down_sync(0xffffffffu, a0, o);
            a1 += __shfl_down_sync(0xffffffffu, a1, o);
        }
        if (lid == 0) {
            atomicAdd(dst + s0 * 8, a0);
            if (s0 + 1 < NS && (s0 + 1) * H < r1) atomicAdd(dst + (s0 + 1) * 8, a1);
        }
    }
    __syncthreads();
}

extern "C" __global__ void __launch_bounds__(TPB, 3)
cg_persistent(const float* __restrict__ Bin, const float* __restrict__ wc,
              const float* __restrict__ wr, float* __restrict__ x, int G)
{
    unsigned int gen = g_bar_phase;   // survives graph replays
    const int bi = blockIdx.x;
    const int r0 = (int)(((long long)bi * RTOT) / G);
    const int r1 = (int)(((long long)(bi + 1) * RTOT) / G);
    const int s0 = r0 >> 9;
    const int rowlane = threadIdx.x >> 7;
    const int j0 = (threadIdx.x & 127) << 2;

    // Phase Z: zero all accumulator slots (graph replays leave stale data)
    if (bi == 0) {
        for (int t = threadIdx.x; t < 3 * NS * 8; t += TPB) {
            (&g_pAp[0][0])[t] = 0.f;
            (&g_rr[0][0])[t] = 0.f;
        }
    }
    grid_barrier(G, gen);

    // Setup: x = B, r = p = B - A*B, rr0 -> slot 2
    {
        float a0 = 0.f, a1 = 0.f;
        for (int row = r0 + rowlane; row < r1; row += ROWSTEP) {
            int s = row >> 9, i = row & (H - 1);
            int b = s / CH;
            float4 xc, y;
            apply_A(Bin + s * SYS, wc + b * WCN, wr + b * WRN, i, j0, xc, y);
            float4 rv = make_float4(xc.x - y.x, xc.y - y.y, xc.z - y.z, xc.w - y.w);
            int gi = s * SYS + i * W + j0;
            st4(g_r + gi, rv); st4(g_p + gi, rv); st4(x + gi, xc);
            float d = rv.x * rv.x + rv.y * rv.y + rv.z * rv.z + rv.w * rv.w;
            if (s == s0) a0 += d; else a1 += d;
        }
        reduce2_atomic(a0, a1, s0, r1, g_rr[2]);
    }
    grid_barrier(G, gen);

    for (int it = 0; it < MAXIT; ++it) {
        const int cur = it % 3, prev = (it + 2) % 3, nxt = (it + 1) % 3;

        // P1: Ap = A*p ; pAp partials
        {
            float a0 = 0.f, a1 = 0.f;
            for (int row = r0 + rowlane; row < r1; row += ROWSTEP) {
                int s = row >> 9, i = row & (H - 1);
                int b = s / CH;
                float4 pv, y;
                apply_A(g_p + s * SYS, wc + b * WCN, wr + b * WRN, i, j0, pv, y);
                int gi = s * SYS + i * W + j0;
                st4(g_Ap + gi, y);
                float d = pv.x * y.x + pv.y * y.y + pv.z * y.z + pv.w * y.w;
                if (s == s0) a0 += d; else a1 += d;
            }
            reduce2_atomic(a0, a1, s0, r1, g_pAp[cur]);
        }
        grid_barrier(G, gen);

        // P2: alpha = rr/pAp ; x += a p ; r -= a Ap ; rr_new partials
        {
            float a0 = 0.f, a1 = 0.f;
            for (int row = r0 + rowlane; row < r1; row += ROWSTEP) {
                int s = row >> 9, i = row & (H - 1);
                float alpha = nan0(g_rr[prev][s * 8] / g_pAp[cur][s * 8]);
                int gi = s * SYS + i * W + j0;
                float4 xv = ld4(x + gi), pv = ld4(g_p + gi);
                float4 rv = ld4(g_r + gi), av = ld4(g_Ap + gi);
                xv.x += alpha * pv.x; xv.y += alpha * pv.y;
                xv.z += alpha * pv.z; xv.w += alpha * pv.w;
                rv.x -= alpha * av.x; rv.y -= alpha * av.y;
                rv.z -= alpha * av.z; rv.w -= alpha * av.w;
                st4(x + gi, xv); st4(g_r + gi, rv);
                float d = rv.x * rv.x + rv.y * rv.y + rv.z * rv.z + rv.w * rv.w;
                if (s == s0) a0 += d; else a1 += d;
            }
            reduce2_atomic(a0, a1, s0, r1, g_rr[cur]);
        }
        grid_barrier(G, gen);

        // P3: convergence test ; p = r + beta*p ; zero next accumulator slot
        __shared__ int s_done;
        if (threadIdx.x == 0) {
            float tot = 0.f;
            for (int s = 0; s < NS; ++s) tot += g_rr[cur][s * 8];
            s_done = (tot < EPS_F) ? 1 : 0;
        }
        __syncthreads();
        if (s_done) break;   // uniform decision across all blocks

        for (int row = r0 + rowlane; row < r1; row += ROWSTEP) {
            int s = row >> 9, i = row & (H - 1);
            float beta = nan0(g_rr[cur][s * 8] / g_rr[prev][s * 8]);
            int gi = s * SYS + i * W + j0;
            float4 rv = ld4(g_r + gi), pv = ld4(g_p + gi);
            pv.x = rv.x + beta * pv.x; pv.y = rv.y + beta * pv.y;
            pv.z = rv.z + beta * pv.z; pv.w = rv.w + beta * pv.w;
            st4(g_p + gi, pv);
        }
        if (bi == 0) {
            for (int t = threadIdx.x; t < NS * 8; t += TPB) {
                g_pAp[nxt][t] = 0.f;
                g_rr[nxt][t] = 0.f;
            }
        }
        grid_barrier(G, gen);
    }
}

extern "C" void kernel_launch(void* const* d_in, const int* in_sizes, int n_in,
                              void* d_out, int out_size)
{
    static int G = 0;
    if (G == 0) {
        int dev = 0;
        cudaGetDevice(&dev);
        int sms = 0;
        cudaDeviceGetAttribute(&sms, cudaDevAttrMultiProcessorCount, dev);
        int occ = 0;
        cudaOccupancyMaxActiveBlocksPerMultiprocessor(&occ, cg_persistent, TPB, 0);
        if (occ < 1) occ = 1;
        G = sms * occ;
        if (G > RTOT) G = RTOT;
    }
    cg_persistent<<<G, TPB>>>((const float*)d_in[0], (const float*)d_in[1],
                              (const float*)d_in[2], (float*)d_out, G);
}

// round 2
// speedup vs baseline: 1.0049x; 1.0049x over previous
#include <cuda_runtime.h>

#define H 512
#define W 512
#define BSZ 16
#define CH 3
#define NS (BSZ*CH)          // 48 systems
#define SYS (H*W)            // 262144
#define NTOT (NS*SYS)        // 12582912
#define RTOT (NS*H)          // 24576 total rows
#define WCN (511*512)
#define WRN (512*511)
#define MAXIT 100
#define EPS_F 158.32966f     // (1e-6 * 16*3*512*512)^2
#define TPB 512
#define ROWSTEP (TPB/128)    // 4 rows per block step

// Scratch (__device__ globals: allocation-free rule)
__device__ float g_r[NTOT];
__device__ float g_pbuf[2][NTOT];     // double-buffered p (pass1 reads old halo, writes new)
__device__ float g_pAp[3][NS*8];
__device__ float g_rr[3][NS*8];
__device__ unsigned int g_bar_arrive;
__device__ volatile unsigned int g_bar_phase;

__device__ __forceinline__ float4 ld4(const float* p) { return *reinterpret_cast<const float4*>(p); }
__device__ __forceinline__ void st4(float* p, float4 v) { *reinterpret_cast<float4*>(p) = v; }

__device__ __forceinline__ float nan0(float v) {
    if (isnan(v)) return 0.0f;
    if (isinf(v)) return v > 0.f ? 3.402823466e38f : -3.402823466e38f;
    return v;
}

__device__ __forceinline__ void grid_barrier(int G, unsigned int &gen) {
    __syncthreads();
    if (threadIdx.x == 0) {
        __threadfence();
        unsigned int t = atomicAdd(&g_bar_arrive, 1u);
        if (t == (unsigned int)(G - 1)) {
            g_bar_arrive = 0;
            __threadfence();
            g_bar_phase = gen + 1u;
        } else {
            while (g_bar_phase == gen) { __nanosleep(64); }
        }
        gen++;
        __threadfence();
    }
    __syncthreads();
}

// y = (I + L_w) z  at (i, j0..j0+3), where the source field z is either
//   COMBINE=0:  z = ra
//   COMBINE=1:  z = ra + beta * pb     (formed on the fly, incl. halo points)
// Diagonal built implicitly: y = z + sum_edges w*(z - z_nbr).
template<int COMBINE>
__device__ __forceinline__ void apply_A_gen(
    const float* __restrict__ ra, const float* __restrict__ pb, float beta,
    const float* __restrict__ wcb, const float* __restrict__ wrb,
    int i, int j0, float4 &xc, float4 &y)
{
    int idx = i * W + j0;
    float4 vc = ld4(ra + idx);
    if (COMBINE) {
        float4 q = ld4(pb + idx);
        vc.x += beta * q.x; vc.y += beta * q.y; vc.z += beta * q.z; vc.w += beta * q.w;
    }
    xc = vc;
    float y0 = vc.x, y1 = vc.y, y2 = vc.z, y3 = vc.w;
    if (i > 0) {
        float4 xu = ld4(ra + idx - W);
        if (COMBINE) {
            float4 q = ld4(pb + idx - W);
            xu.x += beta * q.x; xu.y += beta * q.y; xu.z += beta * q.z; xu.w += beta * q.w;
        }
        float4 wu = ld4(wcb + (i - 1) * W + j0);
        y0 += wu.x * (vc.x - xu.x); y1 += wu.y * (vc.y - xu.y);
        y2 += wu.z * (vc.z - xu.z); y3 += wu.w * (vc.w - xu.w);
    }
    if (i < H - 1) {
        float4 xd = ld4(ra + idx + W);
        if (COMBINE) {
            float4 q = ld4(pb + idx + W);
            xd.x += beta * q.x; xd.y += beta * q.y; xd.z += beta * q.z; xd.w += beta * q.w;
        }
        float4 wd = ld4(wcb + i * W + j0);
        y0 += wd.x * (vc.x - xd.x); y1 += wd.y * (vc.y - xd.y);
        y2 += wd.z * (vc.z - xd.z); y3 += wd.w * (vc.w - xd.w);
    }
    const float* wrow = wrb + i * 511;
    float w0 = wrow[j0], w1 = wrow[j0 + 1], w2 = wrow[j0 + 2];
    y0 += w0 * (vc.x - vc.y);
    y1 += w0 * (vc.y - vc.x) + w1 * (vc.y - vc.z);
    y2 += w1 * (vc.z - vc.y) + w2 * (vc.z - vc.w);
    y3 += w2 * (vc.w - vc.z);
    if (j0 > 0) {
        float xl = ra[idx - 1];
        if (COMBINE) xl += beta * pb[idx - 1];
        y0 += wrow[j0 - 1] * (vc.x - xl);
    }
    if (j0 + 4 < W) {
        float xr = ra[idx + 4];
        if (COMBINE) xr += beta * pb[idx + 4];
        y3 += wrow[j0 + 3] * (vc.w - xr);
    }
    y = make_float4(y0, y1, y2, y3);
}

// Block covers contiguous rows spanning at most 2 systems (s0, s0+1).
__device__ __forceinline__ void reduce2_atomic(float a0, float a1, int s0, int r1, float* dst)
{
    __shared__ float sm[2][TPB / 32];
    #pragma unroll
    for (int o = 16; o; o >>= 1) {
        a0 += __shfl_down_sync(0xffffffffu, a0, o);
        a1 += __shfl_down_sync(0xffffffffu, a1, o);
    }
    int wid = threadIdx.x >> 5, lid = threadIdx.x & 31;
    if (lid == 0) { sm[0][wid] = a0; sm[1][wid] = a1; }
    __syncthreads();
    if (threadIdx.x < 32) {
        a0 = (lid < TPB / 32) ? sm[0][lid] : 0.f;
        a1 = (lid < TPB / 32) ? sm[1][lid] : 0.f;
        #pragma unroll
        for (int o = 16; o; o >>= 1) {
            a0 += __shfl_down_sync(0xffffffffu, a0, o);
            a1 += __shfl_down_sync(0xffffffffu, a1, o);
        }
        if (lid == 0) {
            atomicAdd(dst + s0 * 8, a0);
            if (s0 + 1 < NS && (s0 + 1) * H < r1) atomicAdd(dst + (s0 + 1) * 8, a1);
        }
    }
    __syncthreads();
}

extern "C" __global__ void __launch_bounds__(TPB, 3)
cg_persistent(const float* __restrict__ Bin, const float* __restrict__ wc,
              const float* __restrict__ wr, float* __restrict__ x, int G)
{
    unsigned int gen = g_bar_phase;   // survives graph replays
    const int bi = blockIdx.x;
    const int r0 = (int)(((long long)bi * RTOT) / G);
    const int r1 = (int)(((long long)(bi + 1) * RTOT) / G);
    const int s0 = r0 >> 9;
    const int rowlane = threadIdx.x >> 7;
    const int j0 = (threadIdx.x & 127) << 2;

    // Phase Z: zero all scalar accumulator slots (stale across graph replays)
    if (bi == 0) {
        for (int t = threadIdx.x; t < 3 * NS * 8; t += TPB) {
            (&g_pAp[0][0])[t] = 0.f;
            (&g_rr[0][0])[t] = 0.f;
        }
    }
    grid_barrier(G, gen);

    // Setup: x = B; r0 = B - A*B; rr0 -> slot 0.  (p written by pass1 of it=0)
    {
        float a0 = 0.f, a1 = 0.f;
        for (int row = r0 + rowlane; row < r1; row += ROWSTEP) {
            int s = row >> 9, i = row & (H - 1);
            int b = s / CH;
            float4 xc, y;
            apply_A_gen<0>(Bin + s * SYS, (const float*)0, 0.f,
                           wc + b * WCN, wr + b * WRN, i, j0, xc, y);
            float4 rv = make_float4(xc.x - y.x, xc.y - y.y, xc.z - y.z, xc.w - y.w);
            int gi = s * SYS + i * W + j0;
            st4(g_r + gi, rv); st4(x + gi, xc);
            float d = rv.x * rv.x + rv.y * rv.y + rv.z * rv.z + rv.w * rv.w;
            if (s == s0) a0 += d; else a1 += d;
        }
        reduce2_atomic(a0, a1, s0, r1, g_rr[0]);
    }
    grid_barrier(G, gen);

    for (int it = 0; it < MAXIT; ++it) {
        const int cur = it % 3, prv = (it + 2) % 3, nxt = (it + 1) % 3;
        float* __restrict__ pnew = g_pbuf[it & 1];
        const float* __restrict__ pold = g_pbuf[(it + 1) & 1];

        // ---- Pass 1: p = r + beta*p_old (on the fly, incl. halo); pAp dot; no Ap store
        {
            float a0 = 0.f, a1 = 0.f;
            for (int row = r0 + rowlane; row < r1; row += ROWSTEP) {
                int s = row >> 9, i = row & (H - 1);
                int b = s / CH;
                float4 pc, y;
                int gi = s * SYS + i * W + j0;
                if (it == 0) {
                    apply_A_gen<0>(g_r + s * SYS, (const float*)0, 0.f,
                                   wc + b * WCN, wr + b * WRN, i, j0, pc, y);
                } else {
                    float beta = nan0(g_rr[cur][s * 8] / g_rr[prv][s * 8]);
                    apply_A_gen<1>(g_r + s * SYS, pold + s * SYS, beta,
                                   wc + b * WCN, wr + b * WRN, i, j0, pc, y);
                }
                st4(pnew + gi, pc);
                float d = pc.x * y.x + pc.y * y.y + pc.z * y.z + pc.w * y.w;
                if (s == s0) a0 += d; else a1 += d;
            }
            reduce2_atomic(a0, a1, s0, r1, g_pAp[cur]);
            if (bi == 0) {   // rr_{it-2}: free; must be zero before pass2 accumulates rr_{it+1}
                for (int t = threadIdx.x; t < NS * 8; t += TPB) g_rr[nxt][t] = 0.f;
            }
        }
        grid_barrier(G, gen);

        // ---- Pass 2: recompute Ap from p; r -= a*Ap; x += a*p; rr dot
        {
            float a0 = 0.f, a1 = 0.f;
            for (int row = r0 + rowlane; row < r1; row += ROWSTEP) {
                int s = row >> 9, i = row & (H - 1);
                int b = s / CH;
                float alpha = nan0(g_rr[cur][s * 8] / g_pAp[cur][s * 8]);
                float4 pc, y;
                apply_A_gen<0>(pnew + s * SYS, (const float*)0, 0.f,
                               wc + b * WCN, wr + b * WRN, i, j0, pc, y);
                int gi = s * SYS + i * W + j0;
                float4 rv = ld4(g_r + gi), xv = ld4(x + gi);
                rv.x -= alpha * y.x; rv.y -= alpha * y.y;
                rv.z -= alpha * y.z; rv.w -= alpha * y.w;
                xv.x += alpha * pc.x; xv.y += alpha * pc.y;
                xv.z += alpha * pc.z; xv.w += alpha * pc.w;
                st4(g_r + gi, rv); st4(x + gi, xv);
                float d = rv.x * rv.x + rv.y * rv.y + rv.z * rv.z + rv.w * rv.w;
                if (s == s0) a0 += d; else a1 += d;
            }
            reduce2_atomic(a0, a1, s0, r1, g_rr[nxt]);
            if (bi == 0) {   // pAp_{it-2}: free; must be zero before pass1(it+1)
                for (int t = threadIdx.x; t < NS * 8; t += TPB) g_pAp[nxt][t] = 0.f;
            }
        }
        grid_barrier(G, gen);

        // ---- Convergence (uniform across blocks; x already holds x_{it+1})
        __shared__ int s_done;
        if (threadIdx.x == 0) {
            float tot = 0.f;
            for (int s = 0; s < NS; ++s) tot += g_rr[nxt][s * 8];
            s_done = (tot < EPS_F) ? 1 : 0;
        }
        __syncthreads();
        if (s_done) break;
    }
}

extern "C" void kernel_launch(void* const* d_in, const int* in_sizes, int n_in,
                              void* d_out, int out_size)
{
    static int G = 0;
    if (G == 0) {
        int dev = 0;
        cudaGetDevice(&dev);
        int sms = 0;
        cudaDeviceGetAttribute(&sms, cudaDevAttrMultiProcessorCount, dev);
        int occ = 0;
        cudaOccupancyMaxActiveBlocksPerMultiprocessor(&occ, cg_persistent, TPB, 0);
        if (occ < 1) occ = 1;
        G = sms * occ;
        if (G > RTOT) G = RTOT;
    }
    cg_persistent<<<G, TPB>>>((const float*)d_in[0], (const float*)d_in[1],
                              (const float*)d_in[2], (float*)d_out, G);
}